// round 7
// baseline (speedup 1.0000x reference)
#include <cuda_runtime.h>
#include <cuda_bf16.h>
#include <math.h>

// Problem constants
#define Bc   64
#define Lc   2048
#define Dc   128
#define Hc   4
#define Ac   128
#define Mc   16
#define Vc   100000
#define NNZc 262144
#define HDc  32
#define GAMMAc 0.3
#define BETAc  1.0

typedef unsigned long long ull;

#define FMA2(acc, a, b) asm("fma.rn.f32x2 %0, %1, %2, %0;" : "+l"(acc) : "l"(a), "l"(b))
__device__ __forceinline__ ull pack2(float x, float y) {
    ull d; asm("mov.b64 %0, {%1, %2};" : "=l"(d) : "f"(x), "f"(y)); return d;
}
__device__ __forceinline__ float2 unpack2(ull v) {
    float2 r; asm("mov.b64 {%0, %1}, %2;" : "=f"(r.x), "=f"(r.y) : "l"(v)); return r;
}

// ---------------- scratch (static __device__, no allocation) ----------------
__device__ __align__(16) float  g_sigT[(size_t)Vc * Mc];
__device__ __align__(16) float  g_PhiP[Mc * Ac];
__device__ double g_sizeP[Mc];
__device__ __align__(16) float  g_PhiQ[Bc * Ac];
__device__ double g_psum[Bc * Mc];
__device__ __align__(16) float  g_AQ[Bc * Ac];
__device__ __align__(16) float  g_BP[Mc * Ac];
__device__ __align__(16) float  g_Vp[Mc * HDc];
__device__ __align__(16) float  g_C[Bc * Dc * Hc];   // [b][d][h]

// ---------------- K1: vocab pass (unchanged from 184us version) ----------------
#define SSTR 18
__global__ void __launch_bounds__(512) k1_vocab(const float* __restrict__ phi_logits,
                                                const float* __restrict__ atom_emb) {
    __shared__ __align__(16) float sS[2][32 * SSTR];
    __shared__ __align__(16) float sRed[16 * 128];

    const int t = threadIdx.x;
    const int w = t >> 5, lane = t & 31;
    const int mS = t >> 5, vS = t & 31;

    ull acc2[8][4];
#pragma unroll
    for (int mp = 0; mp < 8; mp++)
#pragma unroll
        for (int c = 0; c < 4; c++) acc2[mp][c] = pack2(0.f, 0.f);
    double szAcc = 0.0;

    const int nTiles = Vc / 32;   // 3125
    int gt = blockIdx.x;
    if (gt >= nTiles) return;

    {
        float x = phi_logits[(size_t)mS * Vc + gt * 32 + vS];
        float s = 1.0f / (1.0f + __expf(-x));
        sS[0][vS * SSTR + mS] = s;
        szAcc += (double)s;
    }
    float4 eA = *reinterpret_cast<const float4*>(&atom_emb[((size_t)gt * 32 + w) * Ac + lane * 4]);
    float4 eB = *reinterpret_cast<const float4*>(&atom_emb[((size_t)gt * 32 + w + 16) * Ac + lane * 4]);
    __syncthreads();

    int cur = 0;
    for (; gt < nTiles; gt += gridDim.x) {
        const int gtn = gt + gridDim.x;
        const bool has = gtn < nTiles;
        float xn = 0.f; float4 eAn, eBn;
        if (has) {
            xn  = phi_logits[(size_t)mS * Vc + gtn * 32 + vS];
            eAn = *reinterpret_cast<const float4*>(&atom_emb[((size_t)gtn * 32 + w) * Ac + lane * 4]);
            eBn = *reinterpret_cast<const float4*>(&atom_emb[((size_t)gtn * 32 + w + 16) * Ac + lane * 4]);
        }
        {
            int v2 = t >> 4, m2 = t & 15;
            g_sigT[((size_t)gt * 32 + v2) * 16 + m2] = sS[cur][v2 * SSTR + m2];
        }
        {
            ull eDA[4], eDB[4];
            eDA[0] = pack2(eA.x, eA.x); eDA[1] = pack2(eA.y, eA.y);
            eDA[2] = pack2(eA.z, eA.z); eDA[3] = pack2(eA.w, eA.w);
            eDB[0] = pack2(eB.x, eB.x); eDB[1] = pack2(eB.y, eB.y);
            eDB[2] = pack2(eB.z, eB.z); eDB[3] = pack2(eB.w, eB.w);
            const ull* spA = reinterpret_cast<const ull*>(&sS[cur][w * SSTR]);
            const ull* spB = reinterpret_cast<const ull*>(&sS[cur][(w + 16) * SSTR]);
#pragma unroll
            for (int mp = 0; mp < 8; mp++) {
                ull sA2 = spA[mp];
                ull sB2 = spB[mp];
#pragma unroll
                for (int c = 0; c < 4; c++) {
                    FMA2(acc2[mp][c], sA2, eDA[c]);
                    FMA2(acc2[mp][c], sB2, eDB[c]);
                }
            }
        }
        if (has) {
            float s = 1.0f / (1.0f + __expf(-xn));
            sS[cur ^ 1][vS * SSTR + mS] = s;
            szAcc += (double)s;
        }
        __syncthreads();
        eA = eAn; eB = eBn; cur ^= 1;
    }

    {
        double s = szAcc;
#pragma unroll
        for (int k = 16; k; k >>= 1) s += __shfl_xor_sync(0xffffffffu, s, k);
        if (lane == 0) atomicAdd(&g_sizeP[w], s);
    }
    for (int m = 0; m < 16; m++) {
        const int mp = m >> 1, hi = m & 1;
        __syncthreads();
        float4 v;
        float2 u0 = unpack2(acc2[mp][0]);
        float2 u1 = unpack2(acc2[mp][1]);
        float2 u2 = unpack2(acc2[mp][2]);
        float2 u3 = unpack2(acc2[mp][3]);
        v.x = hi ? u0.y : u0.x; v.y = hi ? u1.y : u1.x;
        v.z = hi ? u2.y : u2.x; v.w = hi ? u3.y : u3.x;
        *reinterpret_cast<float4*>(&sRed[w * 128 + lane * 4]) = v;
        __syncthreads();
        if (t < 128) {
            float s = 0.f;
#pragma unroll
            for (int w2 = 0; w2 < 16; w2++) s += sRed[w2 * 128 + t];
            atomicAdd(&g_PhiP[m * Ac + t], s);
        }
    }
}

// ---------------- K2: nnz gather (unchanged from 184us version) ----------------
#define K2_CHUNK 128
__global__ void __launch_bounds__(128) k2_nnz(const int* __restrict__ qids,
                                              const int* __restrict__ qoffs,
                                              const float* __restrict__ atom_emb) {
    __shared__ int sOffs[Bc + 1];
    __shared__ int sIds[K2_CHUNK];
    const int t = threadIdx.x;
    if (t < Bc + 1) sOffs[t] = qoffs[t];
    const int i0 = blockIdx.x * K2_CHUNK;
    sIds[t] = qids[i0 + t];
    __syncthreads();

    int lo = 0, hi = Bc - 1;
    while (lo < hi) { int mid = (lo + hi) >> 1; if (sOffs[mid + 1] <= i0) lo = mid + 1; else hi = mid; }
    int seg = lo;
    int nxt = sOffs[seg + 1];

    float accQ = 0.f;
    double accP = 0.0;
    bool dirty = false;
    const int iend = i0 + K2_CHUNK;
    int i = i0;
    while (i < iend) {
        if (i >= nxt) {
            if (dirty) {
                atomicAdd(&g_PhiQ[seg * Ac + t], accQ);
                if (t < 16) atomicAdd(&g_psum[seg * 16 + t], accP);
                accQ = 0.f; accP = 0.0; dirty = false;
            }
            do { seg++; nxt = sOffs[seg + 1]; } while (i >= nxt);
        }
        int lim = nxt < iend ? nxt : iend;
        int cnt = lim - i;
        int base = i - i0;
        dirty = true;
        int k = 0;
        for (; k + 8 <= cnt; k += 8) {
            int id[8];
#pragma unroll
            for (int j = 0; j < 8; j++) id[j] = sIds[base + k + j];
            float a[8];
#pragma unroll
            for (int j = 0; j < 8; j++) a[j] = atom_emb[(size_t)id[j] * Ac + t];
            accQ += ((a[0] + a[1]) + (a[2] + a[3])) + ((a[4] + a[5]) + (a[6] + a[7]));
            if (t < 16) {
                double s = 0.0;
#pragma unroll
                for (int j = 0; j < 8; j++) s += (double)g_sigT[(size_t)id[j] * 16 + t];
                accP += s;
            }
        }
        for (; k < cnt; k++) {
            int id = sIds[base + k];
            accQ += atom_emb[(size_t)id * Ac + t];
            if (t < 16) accP += (double)g_sigT[(size_t)id * 16 + t];
        }
        i = lim;
    }
    if (dirty) {
        atomicAdd(&g_PhiQ[seg * Ac + t], accQ);
        if (t < 16) atomicAdd(&g_psum[seg * 16 + t], accP);
    }
}

// ---------------- KEPI: fused epilogue, ONE block of 1024 threads ----------------
// Part A: AQ = PhiQ@W_A.T ; BP = PhiP@W_B.T ; Vp = PhiP@W_val.T + b_val
// Part B: fp64 scores -> softmax (smem) -> Z (smem)
// Part C: C[b][d][h] = sum_j W_out[d][h*32+j] * Z[b][j]
__global__ void __launch_bounds__(1024) kepi(const int*   __restrict__ qoffs,
                                             const float* __restrict__ W_A,
                                             const float* __restrict__ W_B,
                                             const float* __restrict__ W_val,
                                             const float* __restrict__ b_val,
                                             const float* __restrict__ W_out,
                                             const float* __restrict__ size_w) {
    __shared__ float sAttn[Bc * Mc];
    __shared__ __align__(16) float sZ[Bc * HDc];
    const int t = threadIdx.x;
    const int g = t >> 7, l = t & 127;

    // -------- Part A --------
    for (int u = g; u < Bc + Mc; u += 8) {
        if (u < Bc) {
            const float4* pv = reinterpret_cast<const float4*>(&g_PhiQ[u * Ac]);
            const float4* wr = reinterpret_cast<const float4*>(&W_A[l * Ac]);
            float acc = 0.f;
#pragma unroll 16
            for (int a = 0; a < Ac / 4; a++) {
                float4 w4 = wr[a], v4 = pv[a];
                acc += w4.x * v4.x + w4.y * v4.y + w4.z * v4.z + w4.w * v4.w;
            }
            g_AQ[u * Ac + l] = acc;
        } else {
            int m = u - Bc;
            const float4* pv = reinterpret_cast<const float4*>(&g_PhiP[m * Ac]);
            const float4* wr = reinterpret_cast<const float4*>(&W_B[l * Ac]);
            float acc = 0.f;
#pragma unroll 16
            for (int a = 0; a < Ac / 4; a++) {
                float4 w4 = wr[a], v4 = pv[a];
                acc += w4.x * v4.x + w4.y * v4.y + w4.z * v4.z + w4.w * v4.w;
            }
            g_BP[m * Ac + l] = acc;
            if (l < HDc) {
                const float4* wv = reinterpret_cast<const float4*>(&W_val[l * Ac]);
                float a2 = 0.f;
#pragma unroll 16
                for (int a = 0; a < Ac / 4; a++) {
                    float4 w4 = wv[a], v4 = pv[a];
                    a2 += w4.x * v4.x + w4.y * v4.y + w4.z * v4.z + w4.w * v4.w;
                }
                g_Vp[m * HDc + l] = a2 + b_val[l];
            }
        }
    }
    __syncthreads();

    // -------- Part B: scores + softmax --------
    {
        const int b = t >> 4, m = t & 15;
        float dotv = 0.f;
        const float4* aq = reinterpret_cast<const float4*>(&g_AQ[b * Ac]);
        const float4* bp = reinterpret_cast<const float4*>(&g_BP[m * Ac]);
#pragma unroll 8
        for (int i = 0; i < Ac / 4; i++) {
            float4 a4 = aq[i], b4 = bp[i];
            dotv += a4.x * b4.x + a4.y * b4.y + a4.z * b4.z + a4.w * b4.w;
        }
        double szQ = (double)(qoffs[b + 1] - qoffs[b]);
        double szP = g_sizeP[m];
        double delta = szQ + szP - 2.0 * g_psum[b * 16 + m];
        double score = -GAMMAc * delta + BETAc * (double)dotv
                     + (double)size_w[0] * szQ + (double)size_w[1] * szP;
        double mx = score;
#pragma unroll
        for (int k = 8; k; k >>= 1) mx = fmax(mx, __shfl_xor_sync(0xffffffffu, mx, k));
        double e = exp(score - mx);
        double ssum = e;
#pragma unroll
        for (int k = 8; k; k >>= 1) ssum += __shfl_xor_sync(0xffffffffu, ssum, k);
        sAttn[t] = (float)(e / ssum);
    }
    __syncthreads();

    // Z into smem
    for (int o = t; o < Bc * HDc; o += 1024) {
        int bb = o >> 5, hd = o & 31;
        float z = 0.f;
#pragma unroll
        for (int mm = 0; mm < 16; mm++) z += sAttn[bb * 16 + mm] * g_Vp[mm * HDc + hd];
        sZ[o] = z;
    }
    __syncthreads();

    // -------- Part C --------
#pragma unroll
    for (int i = 0; i < 8; i++) {
        const int ud = t + i * 1024;            // (b,d) unit
        const int b = ud >> 7, d = ud & 127;
        float4 acc;
        const float* zr = &sZ[b * HDc];
        {
            float a0 = 0.f, a1 = 0.f, a2 = 0.f, a3 = 0.f;
            const float* wr = &W_out[d * Dc];
#pragma unroll 8
            for (int j = 0; j < HDc; j++) {
                float zj = zr[j];
                a0 = fmaf(wr[j], zj, a0);
                a1 = fmaf(wr[HDc + j], zj, a1);
                a2 = fmaf(wr[2 * HDc + j], zj, a2);
                a3 = fmaf(wr[3 * HDc + j], zj, a3);
            }
            acc = make_float4(a0, a1, a2, a3);
        }
        *reinterpret_cast<float4*>(&g_C[ud * Hc]) = acc;
    }
}

// ---------------- K5: token pass, two-stage via smem (no big shuffles) ----------------
// Block = 256 threads, tile = 64 tokens (one block never straddles b: 64 | 2048).
#define K5_TOK 64
#define XSTR 132   // padded row stride (floats); 132*4=528B, 16B-aligned per row
__global__ void __launch_bounds__(256) k5_tokens(const float* __restrict__ ts,
                                                 const float* __restrict__ W_gate,
                                                 const float* __restrict__ b_gate,
                                                 const float* __restrict__ b_out,
                                                 float* __restrict__ out) {
    __shared__ __align__(16) float sx[K5_TOK * XSTR];
    __shared__ __align__(16) float sg[K5_TOK * 4];
    const int t = threadIdx.x;
    const int u = blockIdx.x;                 // 2048 blocks
    const int b = u >> 5;                     // 32 blocks per batch row (2048/64)
    const float* xb = ts + (size_t)u * K5_TOK * Dc;
    float* ob = out + (size_t)u * K5_TOK * Dc;

    // stage 0: load 64x128 tile into padded smem (2048 float4s)
#pragma unroll
    for (int i = 0; i < 8; i++) {
        int idx = t + i * 256;
        int tok = idx >> 5, d4 = idx & 31;
        float4 v = *reinterpret_cast<const float4*>(&xb[idx * 4]);
        *reinterpret_cast<float4*>(&sx[tok * XSTR + d4 * 4]) = v;
    }
    __syncthreads();

    // stage 1: gate logits. thread t -> token t>>2, head t&3.
    {
        const int tok = t >> 2, h = t & 3;
        const float4* wg = reinterpret_cast<const float4*>(&W_gate[h * Dc]);
        const float4* xr = reinterpret_cast<const float4*>(&sx[tok * XSTR]);
        float p = 0.f;
#pragma unroll 8
        for (int i = 0; i < Dc / 4; i++) {
            float4 x = xr[i], w = wg[i];
            p += x.x * w.x + x.y * w.y + x.z * w.z + x.w * w.w;
        }
        p += b_gate[h];
        float mx = p;
        mx = fmaxf(mx, __shfl_xor_sync(0xffffffffu, mx, 1));
        mx = fmaxf(mx, __shfl_xor_sync(0xffffffffu, mx, 2));
        float e = __expf(p - mx);
        float s = e;
        s += __shfl_xor_sync(0xffffffffu, s, 1);
        s += __shfl_xor_sync(0xffffffffu, s, 2);
        sg[tok * 4 + h] = e / s;
    }
    __syncthreads();

    // stage 2: out[tok, d] = b_out[d] + sum_h g[h] * C[b][d][h]
    {
        const int lane = t & 31, wrp = t >> 5;   // 8 warps, 8 token-groups
        const int d0 = lane * 4;
        float4 c[4];
#pragma unroll
        for (int j = 0; j < 4; j++) c[j] = *reinterpret_cast<const float4*>(&g_C[(b * Dc + d0 + j) * Hc]);
        const float4 bo = *reinterpret_cast<const float4*>(&b_out[d0]);
#pragma unroll
        for (int k = 0; k < 8; k++) {
            const int tok = wrp + k * 8;
            const float4 gv = *reinterpret_cast<const float4*>(&sg[tok * 4]);
            float4 o;
            o.x = bo.x + gv.x * c[0].x + gv.y * c[0].y + gv.z * c[0].z + gv.w * c[0].w;
            o.y = bo.y + gv.x * c[1].x + gv.y * c[1].y + gv.z * c[1].z + gv.w * c[1].w;
            o.z = bo.z + gv.x * c[2].x + gv.y * c[2].y + gv.z * c[2].z + gv.w * c[2].w;
            o.w = bo.w + gv.x * c[3].x + gv.y * c[3].y + gv.z * c[3].z + gv.w * c[3].w;
            *reinterpret_cast<float4*>(&ob[tok * Dc + d0]) = o;
        }
    }
}

// ---------------- launcher ----------------
extern "C" void kernel_launch(void* const* d_in, const int* in_sizes, int n_in,
                              void* d_out, int out_size) {
    const float* token_states = (const float*)d_in[0];
    const int*   query_ids    = (const int*)d_in[1];
    const int*   query_offs   = (const int*)d_in[2];
    const float* atom_emb     = (const float*)d_in[3];
    const float* phi_logits   = (const float*)d_in[4];
    const float* W_A          = (const float*)d_in[5];
    const float* W_B          = (const float*)d_in[6];
    const float* W_val        = (const float*)d_in[7];
    const float* b_val        = (const float*)d_in[8];
    const float* W_gate       = (const float*)d_in[9];
    const float* b_gate       = (const float*)d_in[10];
    const float* W_out        = (const float*)d_in[11];
    const float* b_out        = (const float*)d_in[12];
    const float* size_w       = (const float*)d_in[13];
    float* out = (float*)d_out;

    // zero accumulators via memset nodes (cheaper than a kernel)
    void *pPhiP, *pPhiQ, *pSizeP, *pPsum;
    cudaGetSymbolAddress(&pPhiP, g_PhiP);
    cudaGetSymbolAddress(&pPhiQ, g_PhiQ);
    cudaGetSymbolAddress(&pSizeP, g_sizeP);
    cudaGetSymbolAddress(&pPsum, g_psum);
    cudaMemsetAsync(pPhiP, 0, Mc * Ac * sizeof(float));
    cudaMemsetAsync(pPhiQ, 0, Bc * Ac * sizeof(float));
    cudaMemsetAsync(pSizeP, 0, Mc * sizeof(double));
    cudaMemsetAsync(pPsum, 0, Bc * Mc * sizeof(double));

    k1_vocab<<<148, 512>>>(phi_logits, atom_emb);
    k2_nnz<<<NNZc / K2_CHUNK, 128>>>(query_ids, query_offs, atom_emb);
    kepi<<<1, 1024>>>(query_offs, W_A, W_B, W_val, b_val, W_out, size_w);
    k5_tokens<<<Bc * Lc / K5_TOK, 256>>>(token_states, W_gate, b_gate, b_out, out);
}